// round 1
// baseline (speedup 1.0000x reference)
#include <cuda_runtime.h>
#include <math.h>

#define DIM   768
#define HEADS 12
#define HD    64
#define BS    32
#define NMM   256
#define NV    196
#define NA    60
#define NSRC  256            // NV + NA
#define MQ    (BS * NMM)     // 8192

// Scratch (static __device__ globals; allocation is forbidden)
__device__ float g_Q [(size_t)MQ * DIM];          // 25 MB  [b*256+q][h*64+d]
__device__ float g_KV[(size_t)BS * NSRC * 2*DIM]; // 50 MB  [b*256+t][c*768+h*64+d]
__device__ float g_O [(size_t)MQ * DIM];          // 25 MB  [b*256+q][h*64+d]
__device__ float g_attn_fallback[(size_t)BS * HEADS * NMM * NSRC]; // safety if out_size lacks attn

// ---------------------------------------------------------------------------
// Generic 64x64-tile fp32 GEMM: C[M,N] = A[M,K] @ B[K,N] (+bias)
// MODE 0: A is a plain row-major matrix.
// MODE 1: A rows come from concat(xv[NV rows/batch], xa[NA rows/batch]); K==DIM.
// 256 threads, 4x4 outputs per thread, k-tile 16.
// ---------------------------------------------------------------------------
template<int MODE>
__global__ void __launch_bounds__(256) gemm_tile(
    const float* __restrict__ A, const float* __restrict__ A2,
    const float* __restrict__ B, float* __restrict__ C,
    int M, int N, int K, const float* __restrict__ bias)
{
    __shared__ __align__(16) float Ast[16][68];  // A tile transposed [k][m], padded
    __shared__ __align__(16) float Bs [16][68];  // B tile [k][n], padded

    const int tid = threadIdx.x;
    const int tx  = tid & 15;
    const int ty  = tid >> 4;
    const int m0  = blockIdx.x * 64;
    const int n0  = blockIdx.y * 64;

    float acc[4][4];
#pragma unroll
    for (int i = 0; i < 4; i++)
#pragma unroll
        for (int j = 0; j < 4; j++) acc[i][j] = 0.f;

    for (int k0 = 0; k0 < K; k0 += 16) {
        // load A tile (64 rows x 16 k) -> Ast[k][m]
#pragma unroll
        for (int it = 0; it < 4; it++) {
            int e = tid + it * 256;
            int r = e >> 4, c = e & 15;       // r: tile row, c: k within tile
            float v;
            if (MODE == 0) {
                v = A[(size_t)(m0 + r) * K + (k0 + c)];
            } else {
                int gr = m0 + r;
                int bb = gr >> 8, rr = gr & 255;
                const float* src = (rr < NV)
                    ? (A  + ((size_t)bb * NV + rr) * DIM)
                    : (A2 + ((size_t)bb * NA + (rr - NV)) * DIM);
                v = src[k0 + c];
            }
            Ast[c][r] = v;
        }
        // load B tile (16 k x 64 n)
#pragma unroll
        for (int it = 0; it < 4; it++) {
            int e = tid + it * 256;
            int r = e >> 6, c = e & 63;
            Bs[r][c] = B[(size_t)(k0 + r) * N + (n0 + c)];
        }
        __syncthreads();

#pragma unroll
        for (int kk = 0; kk < 16; kk++) {
            float4 a4 = *(const float4*)&Ast[kk][4 * ty];
            float4 b4 = *(const float4*)&Bs [kk][4 * tx];
            float a[4] = {a4.x, a4.y, a4.z, a4.w};
            float b[4] = {b4.x, b4.y, b4.z, b4.w};
#pragma unroll
            for (int i = 0; i < 4; i++)
#pragma unroll
                for (int j = 0; j < 4; j++)
                    acc[i][j] = fmaf(a[i], b[j], acc[i][j]);
        }
        __syncthreads();
    }

#pragma unroll
    for (int i = 0; i < 4; i++)
#pragma unroll
        for (int j = 0; j < 4; j++) {
            float v = acc[i][j];
            if (bias) v += bias[n0 + 4 * tx + j];
            C[(size_t)(m0 + 4 * ty + i) * N + (n0 + 4 * tx + j)] = v;
        }
}

// ---------------------------------------------------------------------------
// Fused attention per (b, h, 64-query tile):
//   S = Q Kt * scale  ->  softmax rows  ->  attn out + P@V  ->  O
// smem: Qs[64][65] | Kt[64][260] | Vs[256][68] ; Ps[64][260] overlays Qs+Kt.
// ---------------------------------------------------------------------------
#define ATTN_SMEM_FLOATS (64*65 + 64*260 + 256*68)   // 38208
#define ATTN_SMEM_BYTES  (ATTN_SMEM_FLOATS * 4)      // 152832

__global__ void __launch_bounds__(256) attn_kernel(
    const float* __restrict__ Q, const float* __restrict__ KV,
    float* __restrict__ attn, float* __restrict__ O)
{
    extern __shared__ __align__(16) float smem[];
    float* Qs = smem;                   // stride 65
    float* Kt = smem + 64 * 65;         // stride 260 (d-major: Kt[d][j])
    float* Vs = Kt + 64 * 260;          // stride 68  (Vs[j][d])
    float* Ps = smem;                   // stride 260, overlays Qs+Kt after S phase

    const int tid = threadIdx.x;
    const int tx  = tid & 15;
    const int ty  = tid >> 4;
    const int b   = blockIdx.z;
    const int h   = blockIdx.y;
    const int q0  = blockIdx.x * 64;

    // --- load tiles ---
    const float* Qg = Q + ((size_t)(b * NMM + q0)) * DIM + h * HD;
#pragma unroll 4
    for (int it = 0; it < 16; it++) {
        int e = tid + it * 256;
        int i = e >> 6, d = e & 63;
        Qs[i * 65 + d] = Qg[(size_t)i * DIM + d];
    }
    const float* Kg = KV + ((size_t)b * NSRC) * (2 * DIM) + h * HD;
    const float* Vg = Kg + DIM;
#pragma unroll 8
    for (int it = 0; it < 64; it++) {
        int e = tid + it * 256;
        int j = e >> 6, d = e & 63;
        float kv_ = Kg[(size_t)j * (2 * DIM) + d];
        float vv_ = Vg[(size_t)j * (2 * DIM) + d];
        Kt[d * 260 + j] = kv_;
        Vs[j * 68 + d]  = vv_;
    }
    __syncthreads();

    // --- S = Q @ K^T : thread owns rows 4ty+i (i<4), cols 16tx+j (j<16) ---
    float acc[4][16];
#pragma unroll
    for (int i = 0; i < 4; i++)
#pragma unroll
        for (int j = 0; j < 16; j++) acc[i][j] = 0.f;

#pragma unroll 4
    for (int dd = 0; dd < 64; dd++) {
        float a[4];
#pragma unroll
        for (int i = 0; i < 4; i++) a[i] = Qs[(4 * ty + i) * 65 + dd];
        const float* kr = &Kt[dd * 260 + 16 * tx];
        float4 b0 = *(const float4*)(kr + 0);
        float4 b1 = *(const float4*)(kr + 4);
        float4 b2 = *(const float4*)(kr + 8);
        float4 b3 = *(const float4*)(kr + 12);
        float bv[16] = {b0.x, b0.y, b0.z, b0.w, b1.x, b1.y, b1.z, b1.w,
                        b2.x, b2.y, b2.z, b2.w, b3.x, b3.y, b3.z, b3.w};
#pragma unroll
        for (int i = 0; i < 4; i++)
#pragma unroll
            for (int j = 0; j < 16; j++)
                acc[i][j] = fmaf(a[i], bv[j], acc[i][j]);
    }

    // --- softmax over the 256-wide row (16 threads with same ty hold one row) ---
    const float scale = 0.125f;   // 64^-0.5
#pragma unroll
    for (int i = 0; i < 4; i++) {
        float m = acc[i][0];
#pragma unroll
        for (int j = 1; j < 16; j++) m = fmaxf(m, acc[i][j]);
#pragma unroll
        for (int off = 1; off < 16; off <<= 1)
            m = fmaxf(m, __shfl_xor_sync(0xffffffffu, m, off));
        float s = 0.f;
#pragma unroll
        for (int j = 0; j < 16; j++) {
            float p = __expf((acc[i][j] - m) * scale);
            acc[i][j] = p;
            s += p;
        }
#pragma unroll
        for (int off = 1; off < 16; off <<= 1)
            s += __shfl_xor_sync(0xffffffffu, s, off);
        float inv = 1.0f / s;
#pragma unroll
        for (int j = 0; j < 16; j++) acc[i][j] *= inv;
    }
    __syncthreads();   // everyone done reading Qs/Kt before Ps overlay

    // --- write attn (global) + Ps (smem) ---
    float* ag = attn + (((size_t)(b * HEADS + h) * NMM + q0)) * NSRC;
#pragma unroll
    for (int i = 0; i < 4; i++) {
        float* pr = &Ps[(4 * ty + i) * 260 + 16 * tx];
        float* gr = &ag[(size_t)(4 * ty + i) * NSRC + 16 * tx];
#pragma unroll
        for (int j = 0; j < 16; j++) {
            pr[j] = acc[i][j];
            gr[j] = acc[i][j];
        }
    }
    __syncthreads();

    // --- O = P @ V : thread owns rows 4ty+i, out cols 4tx+j ---
    float oacc[4][4];
#pragma unroll
    for (int i = 0; i < 4; i++)
#pragma unroll
        for (int j = 0; j < 4; j++) oacc[i][j] = 0.f;

#pragma unroll 8
    for (int dd = 0; dd < 256; dd++) {
        float a[4];
#pragma unroll
        for (int i = 0; i < 4; i++) a[i] = Ps[(4 * ty + i) * 260 + dd];
        float4 b4 = *(const float4*)&Vs[dd * 68 + 4 * tx];
        float bv[4] = {b4.x, b4.y, b4.z, b4.w};
#pragma unroll
        for (int i = 0; i < 4; i++)
#pragma unroll
            for (int j = 0; j < 4; j++)
                oacc[i][j] = fmaf(a[i], bv[j], oacc[i][j]);
    }

    float* Og = O + ((size_t)(b * NMM + q0)) * DIM + h * HD;
#pragma unroll
    for (int i = 0; i < 4; i++)
#pragma unroll
        for (int j = 0; j < 4; j++)
            Og[(size_t)(4 * ty + i) * DIM + (4 * tx + j)] = oacc[i][j];
}

// ---------------------------------------------------------------------------
extern "C" void kernel_launch(void* const* d_in, const int* in_sizes, int n_in,
                              void* d_out, int out_size)
{
    const float* xmm   = (const float*)d_in[0];
    const float* xv    = (const float*)d_in[1];
    const float* xa    = (const float*)d_in[2];
    const float* Wq    = (const float*)d_in[3];
    const float* Wkv   = (const float*)d_in[4];
    const float* Wproj = (const float*)d_in[5];
    const float* bproj = (const float*)d_in[6];

    float* out = (float*)d_out;

    float *Qb, *KVb, *Ob, *attn_fb;
    cudaGetSymbolAddress((void**)&Qb,      g_Q);
    cudaGetSymbolAddress((void**)&KVb,     g_KV);
    cudaGetSymbolAddress((void**)&Ob,      g_O);
    cudaGetSymbolAddress((void**)&attn_fb, g_attn_fallback);

    // Output tuple assumed concatenated: out [MQ*DIM] then attn [BS*HEADS*NMM*NSRC].
    const size_t out_elems  = (size_t)MQ * DIM;
    const size_t attn_elems = (size_t)BS * HEADS * NMM * NSRC;
    float* attn_out = ((size_t)out_size >= out_elems + attn_elems)
                        ? out + out_elems : attn_fb;

    cudaFuncSetAttribute(attn_kernel,
                         cudaFuncAttributeMaxDynamicSharedMemorySize,
                         ATTN_SMEM_BYTES);

    // 1) Q = xmm @ Wq
    {
        dim3 g(MQ / 64, DIM / 64);
        gemm_tile<0><<<g, 256>>>(xmm, nullptr, Wq, Qb, MQ, DIM, DIM, nullptr);
    }
    // 2) KV = concat(xv, xa) @ Wkv
    {
        dim3 g(MQ / 64, (2 * DIM) / 64);
        gemm_tile<1><<<g, 256>>>(xv, xa, Wkv, KVb, MQ, 2 * DIM, DIM, nullptr);
    }
    // 3) attention: softmax(QK^T * scale) -> attn out, O = P @ V
    {
        dim3 g(NMM / 64, HEADS, BS);
        attn_kernel<<<g, 256, ATTN_SMEM_BYTES>>>(Qb, KVb, attn_out, Ob);
    }
    // 4) out = O @ Wproj + bproj
    {
        dim3 g(MQ / 64, DIM / 64);
        gemm_tile<0><<<g, 256>>>(Ob, nullptr, Wproj, out, MQ, DIM, DIM, bproj);
    }
}

// round 3
// speedup vs baseline: 1.7111x; 1.7111x over previous
#include <cuda_runtime.h>
#include <cuda_bf16.h>
#include <cstdint>
#include <math.h>

#define DIM   768
#define HEADS 12
#define HD    64
#define BS    32
#define NMM   256
#define NV    196
#define NA    60
#define NSRC  256            // NV + NA
#define MQ    (BS * NMM)     // 8192

// ---------------------------------------------------------------------------
// Scratch (static __device__ globals; allocation is forbidden)
// ---------------------------------------------------------------------------
__device__ float g_Q [(size_t)MQ * DIM];
__device__ float g_KV[(size_t)BS * NSRC * 2 * DIM];
__device__ float g_O [(size_t)MQ * DIM];
__device__ float g_attn_fallback[(size_t)BS * HEADS * NMM * NSRC];

__device__ __nv_bfloat16 g_Axmm_hi[(size_t)MQ * DIM];
__device__ __nv_bfloat16 g_Axmm_lo[(size_t)MQ * DIM];
__device__ __nv_bfloat16 g_Asrc_hi[(size_t)MQ * DIM];
__device__ __nv_bfloat16 g_Asrc_lo[(size_t)MQ * DIM];
__device__ __nv_bfloat16 g_AO_hi  [(size_t)MQ * DIM];
__device__ __nv_bfloat16 g_AO_lo  [(size_t)MQ * DIM];
__device__ __nv_bfloat16 g_Wqt_hi [(size_t)DIM * DIM];
__device__ __nv_bfloat16 g_Wqt_lo [(size_t)DIM * DIM];
__device__ __nv_bfloat16 g_Wkvt_hi[(size_t)2 * DIM * DIM];
__device__ __nv_bfloat16 g_Wkvt_lo[(size_t)2 * DIM * DIM];
__device__ __nv_bfloat16 g_Wpt_hi [(size_t)DIM * DIM];
__device__ __nv_bfloat16 g_Wpt_lo [(size_t)DIM * DIM];

// ---------------------------------------------------------------------------
// Conversion kernels: fp32 -> (hi, lo) bf16 split
// ---------------------------------------------------------------------------
__global__ void split_plain(const float* __restrict__ X,
                            __nv_bfloat16* __restrict__ hi,
                            __nv_bfloat16* __restrict__ lo, size_t n) {
    for (size_t i = (size_t)blockIdx.x * blockDim.x + threadIdx.x; i < n;
         i += (size_t)gridDim.x * blockDim.x) {
        float x = X[i];
        __nv_bfloat16 h = __float2bfloat16(x);
        hi[i] = h;
        lo[i] = __float2bfloat16(x - __bfloat162float(h));
    }
}

__global__ void split_concat(const float* __restrict__ xv, const float* __restrict__ xa,
                             __nv_bfloat16* __restrict__ hi, __nv_bfloat16* __restrict__ lo) {
    size_t n = (size_t)MQ * DIM;
    for (size_t i = (size_t)blockIdx.x * blockDim.x + threadIdx.x; i < n;
         i += (size_t)gridDim.x * blockDim.x) {
        size_t row = i / DIM, col = i % DIM;
        int b = (int)(row >> 8), t = (int)(row & 255);
        float x = (t < NV) ? xv[((size_t)b * NV + t) * DIM + col]
                           : xa[((size_t)b * NA + (t - NV)) * DIM + col];
        __nv_bfloat16 h = __float2bfloat16(x);
        hi[i] = h;
        lo[i] = __float2bfloat16(x - __bfloat162float(h));
    }
}

// W [K][N] fp32 -> Wt [N][K] bf16 hi/lo
__global__ void transpose_split(const float* __restrict__ W,
                                __nv_bfloat16* __restrict__ Thi,
                                __nv_bfloat16* __restrict__ Tlo, int K, int N) {
    __shared__ float tile[32][33];
    int n0 = blockIdx.x * 32, k0 = blockIdx.y * 32;
    int tx = threadIdx.x, ty = threadIdx.y;     // (32, 8)
#pragma unroll
    for (int j = 0; j < 32; j += 8)
        tile[ty + j][tx] = W[(size_t)(k0 + ty + j) * N + (n0 + tx)];
    __syncthreads();
#pragma unroll
    for (int j = 0; j < 32; j += 8) {
        float v = tile[tx][ty + j];             // = W[k0+tx][n0+ty+j]
        __nv_bfloat16 h = __float2bfloat16(v);
        size_t o = (size_t)(n0 + ty + j) * K + (k0 + tx);
        Thi[o] = h;
        Tlo[o] = __float2bfloat16(v - __bfloat162float(h));
    }
}

// ---------------------------------------------------------------------------
// HMMA split-bf16 GEMM: C[M,N] = A[M,K] @ Bt[N,K]^T (+bias)
// CTA tile 128x128, 8 warps (2x4), warp tile 64x32, K-chunk 32,
// cp.async double buffer. Smem row stride = 40 bf16 (conflict-free).
// ---------------------------------------------------------------------------
#define CK       32
#define SROW     40                         // bf16 elements per smem row
#define TILE_BF  (128 * SROW)               // per array per stage (elements)
#define ST_ELEMS (4 * TILE_BF)              // Ahi Alo Bhi Blo
#define GEMM_SMEM (2 * ST_ELEMS * 2)        // bytes = 81920

__device__ __forceinline__ void cp_async16(uint32_t saddr, const void* gptr) {
    asm volatile("cp.async.cg.shared.global [%0], [%1], 16;" :: "r"(saddr), "l"(gptr));
}
__device__ __forceinline__ void cp_commit() { asm volatile("cp.async.commit_group;"); }
template<int N_>
__device__ __forceinline__ void cp_wait() { asm volatile("cp.async.wait_group %0;" :: "n"(N_)); }

__device__ __forceinline__ uint32_t smem_u32(const void* p) {
    uint32_t a;
    asm("{ .reg .u64 t; cvta.to.shared.u64 t, %1; cvt.u32.u64 %0, t; }" : "=r"(a) : "l"(p));
    return a;
}

__device__ __forceinline__ void mma16816(float* c, uint32_t a0, uint32_t a1,
                                         uint32_t a2, uint32_t a3,
                                         uint32_t b0, uint32_t b1) {
    asm volatile(
        "mma.sync.aligned.m16n8k16.row.col.f32.bf16.bf16.f32 "
        "{%0,%1,%2,%3}, {%4,%5,%6,%7}, {%8,%9}, {%0,%1,%2,%3};"
        : "+f"(c[0]), "+f"(c[1]), "+f"(c[2]), "+f"(c[3])
        : "r"(a0), "r"(a1), "r"(a2), "r"(a3), "r"(b0), "r"(b1));
}

__global__ void __launch_bounds__(256) gemm_bf16s(
    const __nv_bfloat16* __restrict__ Ahi, const __nv_bfloat16* __restrict__ Alo,
    const __nv_bfloat16* __restrict__ Bhi, const __nv_bfloat16* __restrict__ Blo,
    float* __restrict__ C, int M, int N, int K, const float* __restrict__ bias)
{
    extern __shared__ __align__(16) __nv_bfloat16 sm[];
    // layout per stage: Ahi | Alo | Bhi | Blo, each 128*SROW
    const int tid  = threadIdx.x;
    const int wid  = tid >> 5;
    const int lane = tid & 31;
    const int wm   = (wid >> 2) * 64;        // 0 or 64
    const int wn   = (wid & 3) * 32;         // 0,32,64,96
    const int m0   = blockIdx.y * 128;
    const int n0   = blockIdx.x * 128;
    const int NC   = K / CK;

    const int lr = lane >> 2;                // 0..7
    const int lc = (lane & 3) * 2;           // 0,2,4,6

    float acc[4][4][4];
#pragma unroll
    for (int i = 0; i < 4; i++)
#pragma unroll
        for (int j = 0; j < 4; j++)
#pragma unroll
            for (int v = 0; v < 4; v++) acc[i][j][v] = 0.f;

    uint32_t smb = smem_u32(sm);

    // async-load one chunk (stage s): 512 x 16B segs per array; 2 per thread
    auto load_chunk = [&](int c, int s) {
        uint32_t base = smb + (uint32_t)s * ST_ELEMS * 2;
        int k0 = c * CK;
#pragma unroll
        for (int it = 0; it < 2; it++) {
            int e   = tid + it * 256;
            int r   = e >> 2, seg = e & 3;
            uint32_t doff = (uint32_t)(r * SROW + seg * 8) * 2;
            size_t  goffA = (size_t)(m0 + r) * K + k0 + seg * 8;
            size_t  goffB = (size_t)(n0 + r) * K + k0 + seg * 8;
            cp_async16(base + 0 * TILE_BF * 2 + doff, Ahi + goffA);
            cp_async16(base + 1 * TILE_BF * 2 + doff, Alo + goffA);
            cp_async16(base + 2 * TILE_BF * 2 + doff, Bhi + goffB);
            cp_async16(base + 3 * TILE_BF * 2 + doff, Blo + goffB);
        }
        cp_commit();
    };

    load_chunk(0, 0);

    for (int c = 0; c < NC; c++) {
        int s = c & 1;
        if (c + 1 < NC) load_chunk(c + 1, (c + 1) & 1);
        if (c + 1 < NC) cp_wait<1>(); else cp_wait<0>();
        __syncthreads();

        const __nv_bfloat16* As_hi = sm + (size_t)s * ST_ELEMS + 0 * TILE_BF;
        const __nv_bfloat16* As_lo = As_hi + TILE_BF;
        const __nv_bfloat16* Bs_hi = As_hi + 2 * TILE_BF;
        const __nv_bfloat16* Bs_lo = As_hi + 3 * TILE_BF;

#pragma unroll
        for (int ks = 0; ks < 2; ks++) {
            int kb = ks * 16;
            uint32_t ah[4][4], al[4][4];
#pragma unroll
            for (int mt = 0; mt < 4; mt++) {
                int r = wm + mt * 16 + lr;
                const __nv_bfloat16* ph = As_hi + r * SROW + kb + lc;
                const __nv_bfloat16* pl = As_lo + r * SROW + kb + lc;
                ah[mt][0] = *(const uint32_t*)(ph);
                ah[mt][1] = *(const uint32_t*)(ph + 8 * SROW);
                ah[mt][2] = *(const uint32_t*)(ph + 8);
                ah[mt][3] = *(const uint32_t*)(ph + 8 * SROW + 8);
                al[mt][0] = *(const uint32_t*)(pl);
                al[mt][1] = *(const uint32_t*)(pl + 8 * SROW);
                al[mt][2] = *(const uint32_t*)(pl + 8);
                al[mt][3] = *(const uint32_t*)(pl + 8 * SROW + 8);
            }
            uint32_t bh[4][2], bl[4][2];
#pragma unroll
            for (int nt = 0; nt < 4; nt++) {
                int r = wn + nt * 8 + lr;
                const __nv_bfloat16* ph = Bs_hi + r * SROW + kb + lc;
                const __nv_bfloat16* pl = Bs_lo + r * SROW + kb + lc;
                bh[nt][0] = *(const uint32_t*)(ph);
                bh[nt][1] = *(const uint32_t*)(ph + 8);
                bl[nt][0] = *(const uint32_t*)(pl);
                bl[nt][1] = *(const uint32_t*)(pl + 8);
            }
#pragma unroll
            for (int mt = 0; mt < 4; mt++)
#pragma unroll
                for (int nt = 0; nt < 4; nt++) {
                    mma16816(acc[mt][nt], ah[mt][0], ah[mt][1], ah[mt][2], ah[mt][3],
                             bh[nt][0], bh[nt][1]);
                    mma16816(acc[mt][nt], ah[mt][0], ah[mt][1], ah[mt][2], ah[mt][3],
                             bl[nt][0], bl[nt][1]);
                    mma16816(acc[mt][nt], al[mt][0], al[mt][1], al[mt][2], al[mt][3],
                             bh[nt][0], bh[nt][1]);
                }
        }
        __syncthreads();
    }

    // epilogue
#pragma unroll
    for (int mt = 0; mt < 4; mt++) {
        int r0 = m0 + wm + mt * 16 + lr;
#pragma unroll
        for (int nt = 0; nt < 4; nt++) {
            int cc = n0 + wn + nt * 8 + lc;
            float b0 = bias ? bias[cc]     : 0.f;
            float b1 = bias ? bias[cc + 1] : 0.f;
            float* p0 = C + (size_t)r0 * N + cc;
            float* p1 = C + (size_t)(r0 + 8) * N + cc;
            p0[0] = acc[mt][nt][0] + b0;
            p0[1] = acc[mt][nt][1] + b1;
            p1[0] = acc[mt][nt][2] + b0;
            p1[1] = acc[mt][nt][3] + b1;
        }
    }
}

// ---------------------------------------------------------------------------
// Fused attention per (b, h, 64-query tile) — fp32 SIMT (unchanged)
// ---------------------------------------------------------------------------
#define ATTN_SMEM_FLOATS (64*65 + 64*260 + 256*68)
#define ATTN_SMEM_BYTES  (ATTN_SMEM_FLOATS * 4)

__global__ void __launch_bounds__(256) attn_kernel(
    const float* __restrict__ Q, const float* __restrict__ KV,
    float* __restrict__ attn, float* __restrict__ O)
{
    extern __shared__ __align__(16) float smem[];
    float* Qs = smem;
    float* Kt = smem + 64 * 65;
    float* Vs = Kt + 64 * 260;
    float* Ps = smem;

    const int tid = threadIdx.x;
    const int tx  = tid & 15;
    const int ty  = tid >> 4;
    const int b   = blockIdx.z;
    const int h   = blockIdx.y;
    const int q0  = blockIdx.x * 64;

    const float* Qg = Q + ((size_t)(b * NMM + q0)) * DIM + h * HD;
#pragma unroll 4
    for (int it = 0; it < 16; it++) {
        int e = tid + it * 256;
        int i = e >> 6, d = e & 63;
        Qs[i * 65 + d] = Qg[(size_t)i * DIM + d];
    }
    const float* Kg = KV + ((size_t)b * NSRC) * (2 * DIM) + h * HD;
    const float* Vg = Kg + DIM;
#pragma unroll 8
    for (int it = 0; it < 64; it++) {
        int e = tid + it * 256;
        int j = e >> 6, d = e & 63;
        Kt[d * 260 + j] = Kg[(size_t)j * (2 * DIM) + d];
        Vs[j * 68 + d]  = Vg[(size_t)j * (2 * DIM) + d];
    }
    __syncthreads();

    float acc[4][16];
#pragma unroll
    for (int i = 0; i < 4; i++)
#pragma unroll
        for (int j = 0; j < 16; j++) acc[i][j] = 0.f;

#pragma unroll 4
    for (int dd = 0; dd < 64; dd++) {
        float a[4];
#pragma unroll
        for (int i = 0; i < 4; i++) a[i] = Qs[(4 * ty + i) * 65 + dd];
        const float* kr = &Kt[dd * 260 + 16 * tx];
        float4 b0 = *(const float4*)(kr + 0);
        float4 b1 = *(const float4*)(kr + 4);
        float4 b2 = *(const float4*)(kr + 8);
        float4 b3 = *(const float4*)(kr + 12);
        float bv[16] = {b0.x, b0.y, b0.z, b0.w, b1.x, b1.y, b1.z, b1.w,
                        b2.x, b2.y, b2.z, b2.w, b3.x, b3.y, b3.z, b3.w};
#pragma unroll
        for (int i = 0; i < 4; i++)
#pragma unroll
            for (int j = 0; j < 16; j++)
                acc[i][j] = fmaf(a[i], bv[j], acc[i][j]);
    }

    const float scale = 0.125f;
#pragma unroll
    for (int i = 0; i < 4; i++) {
        float m = acc[i][0];
#pragma unroll
        for (int j = 1; j < 16; j++) m = fmaxf(m, acc[i][j]);
#pragma unroll
        for (int off = 1; off < 16; off <<= 1)
            m = fmaxf(m, __shfl_xor_sync(0xffffffffu, m, off));
        float s = 0.f;
#pragma unroll
        for (int j = 0; j < 16; j++) {
            float p = __expf((acc[i][j] - m) * scale);
            acc[i][j] = p;
            s += p;
        }
#pragma unroll
        for (int off = 1; off < 16; off <<= 1)
            s += __shfl_xor_sync(0xffffffffu, s, off);
        float inv = 1.0f / s;
#pragma unroll
        for (int j = 0; j < 16; j++) acc[i][j] *= inv;
    }
    __syncthreads();

    float* ag = attn + (((size_t)(b * HEADS + h) * NMM + q0)) * NSRC;
#pragma unroll
    for (int i = 0; i < 4; i++) {
        float* pr = &Ps[(4 * ty + i) * 260 + 16 * tx];
        float* gr = &ag[(size_t)(4 * ty + i) * NSRC + 16 * tx];
#pragma unroll
        for (int j = 0; j < 16; j++) { pr[j] = acc[i][j]; gr[j] = acc[i][j]; }
    }
    __syncthreads();

    float oacc[4][4];
#pragma unroll
    for (int i = 0; i < 4; i++)
#pragma unroll
        for (int j = 0; j < 4; j++) oacc[i][j] = 0.f;

#pragma unroll 8
    for (int dd = 0; dd < 256; dd++) {
        float a[4];
#pragma unroll
        for (int i = 0; i < 4; i++) a[i] = Ps[(4 * ty + i) * 260 + dd];
        float4 b4 = *(const float4*)&Vs[dd * 68 + 4 * tx];
        float bv[4] = {b4.x, b4.y, b4.z, b4.w};
#pragma unroll
        for (int i = 0; i < 4; i++)
#pragma unroll
            for (int j = 0; j < 4; j++)
                oacc[i][j] = fmaf(a[i], bv[j], oacc[i][j]);
    }

    float* Og = O + ((size_t)(b * NMM + q0)) * DIM + h * HD;
#pragma unroll
    for (int i = 0; i < 4; i++)
#pragma unroll
        for (int j = 0; j < 4; j++)
            Og[(size_t)(4 * ty + i) * DIM + (4 * tx + j)] = oacc[i][j];
}

// ---------------------------------------------------------------------------
extern "C" void kernel_launch(void* const* d_in, const int* in_sizes, int n_in,
                              void* d_out, int out_size)
{
    const float* xmm   = (const float*)d_in[0];
    const float* xv    = (const float*)d_in[1];
    const float* xa    = (const float*)d_in[2];
    const float* Wq    = (const float*)d_in[3];
    const float* Wkv   = (const float*)d_in[4];
    const float* Wproj = (const float*)d_in[5];
    const float* bproj = (const float*)d_in[6];

    float* out = (float*)d_out;

    float *Qb, *KVb, *Ob, *attn_fb;
    cudaGetSymbolAddress((void**)&Qb,      g_Q);
    cudaGetSymbolAddress((void**)&KVb,     g_KV);
    cudaGetSymbolAddress((void**)&Ob,      g_O);
    cudaGetSymbolAddress((void**)&attn_fb, g_attn_fallback);

    __nv_bfloat16 *Axh, *Axl, *Ash, *Asl, *AOh, *AOl;
    __nv_bfloat16 *Wqh, *Wql, *Wkh, *Wkl, *Wph, *Wpl;
    cudaGetSymbolAddress((void**)&Axh, g_Axmm_hi);
    cudaGetSymbolAddress((void**)&Axl, g_Axmm_lo);
    cudaGetSymbolAddress((void**)&Ash, g_Asrc_hi);
    cudaGetSymbolAddress((void**)&Asl, g_Asrc_lo);
    cudaGetSymbolAddress((void**)&AOh, g_AO_hi);
    cudaGetSymbolAddress((void**)&AOl, g_AO_lo);
    cudaGetSymbolAddress((void**)&Wqh, g_Wqt_hi);
    cudaGetSymbolAddress((void**)&Wql, g_Wqt_lo);
    cudaGetSymbolAddress((void**)&Wkh, g_Wkvt_hi);
    cudaGetSymbolAddress((void**)&Wkl, g_Wkvt_lo);
    cudaGetSymbolAddress((void**)&Wph, g_Wpt_hi);
    cudaGetSymbolAddress((void**)&Wpl, g_Wpt_lo);

    const size_t out_elems  = (size_t)MQ * DIM;
    const size_t attn_elems = (size_t)BS * HEADS * NMM * NSRC;
    float* attn_out = ((size_t)out_size >= out_elems + attn_elems)
                        ? out + out_elems : attn_fb;

    cudaFuncSetAttribute(attn_kernel, cudaFuncAttributeMaxDynamicSharedMemorySize,
                         ATTN_SMEM_BYTES);
    cudaFuncSetAttribute(gemm_bf16s, cudaFuncAttributeMaxDynamicSharedMemorySize,
                         GEMM_SMEM);

    // --- conversions ---
    split_plain<<<512, 256>>>(xmm, Axh, Axl, (size_t)MQ * DIM);
    split_concat<<<512, 256>>>(xv, xa, Ash, Asl);
    {
        dim3 b(32, 8);
        transpose_split<<<dim3(DIM / 32, DIM / 32), b>>>(Wq, Wqh, Wql, DIM, DIM);
        transpose_split<<<dim3(2 * DIM / 32, DIM / 32), b>>>(Wkv, Wkh, Wkl, DIM, 2 * DIM);
        transpose_split<<<dim3(DIM / 32, DIM / 32), b>>>(Wproj, Wph, Wpl, DIM, DIM);
    }

    // --- Q = xmm @ Wq ---
    gemm_bf16s<<<dim3(DIM / 128, MQ / 128), 256, GEMM_SMEM>>>(
        Axh, Axl, Wqh, Wql, Qb, MQ, DIM, DIM, nullptr);
    // --- KV = concat(xv,xa) @ Wkv ---
    gemm_bf16s<<<dim3(2 * DIM / 128, MQ / 128), 256, GEMM_SMEM>>>(
        Ash, Asl, Wkh, Wkl, KVb, MQ, 2 * DIM, DIM, nullptr);
    // --- attention ---
    {
        dim3 g(NMM / 64, HEADS, BS);
        attn_kernel<<<g, 256, ATTN_SMEM_BYTES>>>(Qb, KVb, attn_out, Ob);
    }
    // --- out = O @ Wproj + bproj ---
    split_plain<<<512, 256>>>(Ob, AOh, AOl, (size_t)MQ * DIM);
    gemm_bf16s<<<dim3(DIM / 128, MQ / 128), 256, GEMM_SMEM>>>(
        AOh, AOl, Wph, Wpl, out, MQ, DIM, DIM, bproj);
}

// round 7
// speedup vs baseline: 2.6783x; 1.5653x over previous
#include <cuda_runtime.h>
#include <cuda_bf16.h>
#include <cstdint>
#include <math.h>

#define DIM   768
#define HEADS 12
#define HD    64
#define BS    32
#define NMM   256
#define NV    196
#define NA    60
#define NSRC  256            // NV + NA
#define MQ    (BS * NMM)     // 8192

// ---------------------------------------------------------------------------
// Scratch (static __device__ globals; allocation is forbidden)
// ---------------------------------------------------------------------------
__device__ float g_attn_fallback[(size_t)BS * HEADS * NMM * NSRC];

__device__ __nv_bfloat16 g_Axmm_hi[(size_t)MQ * DIM];
__device__ __nv_bfloat16 g_Axmm_lo[(size_t)MQ * DIM];
__device__ __nv_bfloat16 g_Asrc_hi[(size_t)MQ * DIM];
__device__ __nv_bfloat16 g_Asrc_lo[(size_t)MQ * DIM];
__device__ __nv_bfloat16 g_Qh [(size_t)MQ * DIM];
__device__ __nv_bfloat16 g_Ql [(size_t)MQ * DIM];
__device__ __nv_bfloat16 g_KVh[(size_t)MQ * 2 * DIM];
__device__ __nv_bfloat16 g_KVl[(size_t)MQ * 2 * DIM];
__device__ __nv_bfloat16 g_Oh [(size_t)MQ * DIM];
__device__ __nv_bfloat16 g_Ol [(size_t)MQ * DIM];
__device__ __nv_bfloat16 g_Wqt_hi [(size_t)DIM * DIM];
__device__ __nv_bfloat16 g_Wqt_lo [(size_t)DIM * DIM];
__device__ __nv_bfloat16 g_Wkvt_hi[(size_t)2 * DIM * DIM];
__device__ __nv_bfloat16 g_Wkvt_lo[(size_t)2 * DIM * DIM];
__device__ __nv_bfloat16 g_Wpt_hi [(size_t)DIM * DIM];
__device__ __nv_bfloat16 g_Wpt_lo [(size_t)DIM * DIM];

// ---------------------------------------------------------------------------
// helpers
// ---------------------------------------------------------------------------
__device__ __forceinline__ uint32_t smem_u32(const void* p) {
    uint32_t a;
    asm("{ .reg .u64 t; cvta.to.shared.u64 t, %1; cvt.u32.u64 %0, t; }" : "=r"(a) : "l"(p));
    return a;
}
__device__ __forceinline__ uint32_t pack_bf2(__nv_bfloat16 a, __nv_bfloat16 b) {
    __nv_bfloat162 t = __halves2bfloat162(a, b);
    return *reinterpret_cast<uint32_t*>(&t);
}
__device__ __forceinline__ void split2(float a, float b, uint32_t& hi, uint32_t& lo) {
    __nv_bfloat16 ha = __float2bfloat16(a), hb = __float2bfloat16(b);
    hi = pack_bf2(ha, hb);
    lo = pack_bf2(__float2bfloat16(a - __bfloat162float(ha)),
                  __float2bfloat16(b - __bfloat162float(hb)));
}
__device__ __forceinline__ void cp_async16(uint32_t saddr, const void* gptr) {
    asm volatile("cp.async.cg.shared.global [%0], [%1], 16;" :: "r"(saddr), "l"(gptr));
}
__device__ __forceinline__ void cp_commit() { asm volatile("cp.async.commit_group;"); }
template<int N_>
__device__ __forceinline__ void cp_wait() { asm volatile("cp.async.wait_group %0;" :: "n"(N_)); }

__device__ __forceinline__ void mma16816(float* c, uint32_t a0, uint32_t a1,
                                         uint32_t a2, uint32_t a3,
                                         uint32_t b0, uint32_t b1) {
    asm volatile(
        "mma.sync.aligned.m16n8k16.row.col.f32.bf16.bf16.f32 "
        "{%0,%1,%2,%3}, {%4,%5,%6,%7}, {%8,%9}, {%0,%1,%2,%3};"
        : "+f"(c[0]), "+f"(c[1]), "+f"(c[2]), "+f"(c[3])
        : "r"(a0), "r"(a1), "r"(a2), "r"(a3), "r"(b0), "r"(b1));
}
__device__ __forceinline__ void ldmx2t(uint32_t& r0, uint32_t& r1, uint32_t saddr) {
    asm volatile("ldmatrix.sync.aligned.m8n8.x2.trans.shared.b16 {%0,%1}, [%2];"
                 : "=r"(r0), "=r"(r1) : "r"(saddr));
}
__device__ __forceinline__ void st_cs_f2(float* p, float x, float y) {
    asm volatile("st.global.cs.v2.f32 [%0], {%1, %2};" :: "l"(p), "f"(x), "f"(y) : "memory");
}

// ---------------------------------------------------------------------------
// Conversion kernels: fp32 -> (hi, lo) bf16 split
// ---------------------------------------------------------------------------
__global__ void split_plain(const float* __restrict__ X,
                            __nv_bfloat16* __restrict__ hi,
                            __nv_bfloat16* __restrict__ lo, size_t n) {
    for (size_t i = (size_t)blockIdx.x * blockDim.x + threadIdx.x; i < n;
         i += (size_t)gridDim.x * blockDim.x) {
        float x = X[i];
        __nv_bfloat16 h = __float2bfloat16(x);
        hi[i] = h;
        lo[i] = __float2bfloat16(x - __bfloat162float(h));
    }
}

__global__ void split_concat(const float* __restrict__ xv, const float* __restrict__ xa,
                             __nv_bfloat16* __restrict__ hi, __nv_bfloat16* __restrict__ lo) {
    size_t n = (size_t)MQ * DIM;
    for (size_t i = (size_t)blockIdx.x * blockDim.x + threadIdx.x; i < n;
         i += (size_t)gridDim.x * blockDim.x) {
        size_t row = i / DIM, col = i % DIM;
        int b = (int)(row >> 8), t = (int)(row & 255);
        float x = (t < NV) ? xv[((size_t)b * NV + t) * DIM + col]
                           : xa[((size_t)b * NA + (t - NV)) * DIM + col];
        __nv_bfloat16 h = __float2bfloat16(x);
        hi[i] = h;
        lo[i] = __float2bfloat16(x - __bfloat162float(h));
    }
}

// W [K][N] fp32 -> Wt [N][K] bf16 hi/lo
__global__ void transpose_split(const float* __restrict__ W,
                                __nv_bfloat16* __restrict__ Thi,
                                __nv_bfloat16* __restrict__ Tlo, int K, int N) {
    __shared__ float tile[32][33];
    int n0 = blockIdx.x * 32, k0 = blockIdx.y * 32;
    int tx = threadIdx.x, ty = threadIdx.y;     // (32, 8)
#pragma unroll
    for (int j = 0; j < 32; j += 8)
        tile[ty + j][tx] = W[(size_t)(k0 + ty + j) * N + (n0 + tx)];
    __syncthreads();
#pragma unroll
    for (int j = 0; j < 32; j += 8) {
        float v = tile[tx][ty + j];
        __nv_bfloat16 h = __float2bfloat16(v);
        size_t o = (size_t)(n0 + ty + j) * K + (k0 + tx);
        Thi[o] = h;
        Tlo[o] = __float2bfloat16(v - __bfloat162float(h));
    }
}

// ---------------------------------------------------------------------------
// HMMA split-bf16 GEMM: C[M,N] = A[M,K] @ Bt[N,K]^T
// SPLIT=false: writes fp32 C (+bias). SPLIT=true: writes bf16 hi/lo C.
// ---------------------------------------------------------------------------
#define CK       32
#define SROW     40
#define TILE_BF  (128 * SROW)
#define ST_ELEMS (4 * TILE_BF)
#define GEMM_SMEM (2 * ST_ELEMS * 2)        // 81920 bytes

template<bool SPLIT>
__global__ void __launch_bounds__(256) gemm_bf16s(
    const __nv_bfloat16* __restrict__ Ahi, const __nv_bfloat16* __restrict__ Alo,
    const __nv_bfloat16* __restrict__ Bhi, const __nv_bfloat16* __restrict__ Blo,
    float* __restrict__ C, __nv_bfloat16* __restrict__ Chi, __nv_bfloat16* __restrict__ Clo,
    int M, int N, int K, const float* __restrict__ bias)
{
    extern __shared__ __align__(16) __nv_bfloat16 sm[];
    const int tid  = threadIdx.x;
    const int wid  = tid >> 5;
    const int lane = tid & 31;
    const int wm   = (wid >> 2) * 64;
    const int wn   = (wid & 3) * 32;
    const int m0   = blockIdx.y * 128;
    const int n0   = blockIdx.x * 128;
    const int NC   = K / CK;

    const int lr = lane >> 2;
    const int lc = (lane & 3) * 2;

    float acc[4][4][4];
#pragma unroll
    for (int i = 0; i < 4; i++)
#pragma unroll
        for (int j = 0; j < 4; j++)
#pragma unroll
            for (int v = 0; v < 4; v++) acc[i][j][v] = 0.f;

    uint32_t smb = smem_u32(sm);

    auto load_chunk = [&](int c, int s) {
        uint32_t base = smb + (uint32_t)s * ST_ELEMS * 2;
        int k0 = c * CK;
#pragma unroll
        for (int it = 0; it < 2; it++) {
            int e   = tid + it * 256;
            int r   = e >> 2, seg = e & 3;
            uint32_t doff = (uint32_t)(r * SROW + seg * 8) * 2;
            size_t  goffA = (size_t)(m0 + r) * K + k0 + seg * 8;
            size_t  goffB = (size_t)(n0 + r) * K + k0 + seg * 8;
            cp_async16(base + 0 * TILE_BF * 2 + doff, Ahi + goffA);
            cp_async16(base + 1 * TILE_BF * 2 + doff, Alo + goffA);
            cp_async16(base + 2 * TILE_BF * 2 + doff, Bhi + goffB);
            cp_async16(base + 3 * TILE_BF * 2 + doff, Blo + goffB);
        }
        cp_commit();
    };

    load_chunk(0, 0);

    for (int c = 0; c < NC; c++) {
        int s = c & 1;
        if (c + 1 < NC) load_chunk(c + 1, (c + 1) & 1);
        if (c + 1 < NC) cp_wait<1>(); else cp_wait<0>();
        __syncthreads();

        const __nv_bfloat16* As_hi = sm + (size_t)s * ST_ELEMS + 0 * TILE_BF;
        const __nv_bfloat16* As_lo = As_hi + TILE_BF;
        const __nv_bfloat16* Bs_hi = As_hi + 2 * TILE_BF;
        const __nv_bfloat16* Bs_lo = As_hi + 3 * TILE_BF;

#pragma unroll
        for (int ks = 0; ks < 2; ks++) {
            int kb = ks * 16;
            uint32_t ah[4][4], al[4][4];
#pragma unroll
            for (int mt = 0; mt < 4; mt++) {
                int r = wm + mt * 16 + lr;
                const __nv_bfloat16* ph = As_hi + r * SROW + kb + lc;
                const __nv_bfloat16* pl = As_lo + r * SROW + kb + lc;
                ah[mt][0] = *(const uint32_t*)(ph);
                ah[mt][1] = *(const uint32_t*)(ph + 8 * SROW);
                ah[mt][2] = *(const uint32_t*)(ph + 8);
                ah[mt][3] = *(const uint32_t*)(ph + 8 * SROW + 8);
                al[mt][0] = *(const uint32_t*)(pl);
                al[mt][1] = *(const uint32_t*)(pl + 8 * SROW);
                al[mt][2] = *(const uint32_t*)(pl + 8);
                al[mt][3] = *(const uint32_t*)(pl + 8 * SROW + 8);
            }
            uint32_t bh[4][2], bl[4][2];
#pragma unroll
            for (int nt = 0; nt < 4; nt++) {
                int r = wn + nt * 8 + lr;
                const __nv_bfloat16* ph = Bs_hi + r * SROW + kb + lc;
                const __nv_bfloat16* pl = Bs_lo + r * SROW + kb + lc;
                bh[nt][0] = *(const uint32_t*)(ph);
                bh[nt][1] = *(const uint32_t*)(ph + 8);
                bl[nt][0] = *(const uint32_t*)(pl);
                bl[nt][1] = *(const uint32_t*)(pl + 8);
            }
#pragma unroll
            for (int mt = 0; mt < 4; mt++)
#pragma unroll
                for (int nt = 0; nt < 4; nt++) {
                    mma16816(acc[mt][nt], ah[mt][0], ah[mt][1], ah[mt][2], ah[mt][3],
                             bh[nt][0], bh[nt][1]);
                    mma16816(acc[mt][nt], ah[mt][0], ah[mt][1], ah[mt][2], ah[mt][3],
                             bl[nt][0], bl[nt][1]);
                    mma16816(acc[mt][nt], al[mt][0], al[mt][1], al[mt][2], al[mt][3],
                             bh[nt][0], bh[nt][1]);
                }
        }
        __syncthreads();
    }

#pragma unroll
    for (int mt = 0; mt < 4; mt++) {
        int r0 = m0 + wm + mt * 16 + lr;
#pragma unroll
        for (int nt = 0; nt < 4; nt++) {
            int cc = n0 + wn + nt * 8 + lc;
            if (SPLIT) {
                uint32_t h0, l0, h1, l1;
                split2(acc[mt][nt][0], acc[mt][nt][1], h0, l0);
                split2(acc[mt][nt][2], acc[mt][nt][3], h1, l1);
                *(uint32_t*)(Chi + (size_t)r0 * N + cc)       = h0;
                *(uint32_t*)(Clo + (size_t)r0 * N + cc)       = l0;
                *(uint32_t*)(Chi + (size_t)(r0 + 8) * N + cc) = h1;
                *(uint32_t*)(Clo + (size_t)(r0 + 8) * N + cc) = l1;
            } else {
                float b0 = bias ? bias[cc]     : 0.f;
                float b1 = bias ? bias[cc + 1] : 0.f;
                float* p0 = C + (size_t)r0 * N + cc;
                float* p1 = C + (size_t)(r0 + 8) * N + cc;
                p0[0] = acc[mt][nt][0] + b0;
                p0[1] = acc[mt][nt][1] + b1;
                p1[0] = acc[mt][nt][2] + b0;
                p1[1] = acc[mt][nt][3] + b1;
            }
        }
    }
}

// ---------------------------------------------------------------------------
// HMMA flash-style attention. CTA = (q-tile 128, h, b), 256 thr (8 warps).
// Warp owns 16 q-rows x 256 keys. 3-term split everywhere.
// ---------------------------------------------------------------------------
#define QSTR 72
#define AT_QH 0
#define AT_QL (128 * QSTR)
#define AT_KH (2 * 128 * QSTR)
#define AT_KL (AT_KH + 256 * QSTR)
#define AT_VH (AT_KH + 2 * 256 * QSTR)
#define AT_VL (AT_KH + 3 * 256 * QSTR)
#define AT_SMEM_ELE (AT_KH + 4 * 256 * QSTR)      // 92160 bf16
#define AT_SMEM_BYTES (AT_SMEM_ELE * 2)           // 184320

__global__ void __launch_bounds__(256) attn_mma(
    const __nv_bfloat16* __restrict__ Qhi, const __nv_bfloat16* __restrict__ Qlo,
    const __nv_bfloat16* __restrict__ KVhi, const __nv_bfloat16* __restrict__ KVlo,
    float* __restrict__ attn,
    __nv_bfloat16* __restrict__ Ohi, __nv_bfloat16* __restrict__ Olo)
{
    extern __shared__ __align__(16) __nv_bfloat16 asm_[];
    const int tid  = threadIdx.x;
    const int wid  = tid >> 5;
    const int lane = tid & 31;
    const int lr   = lane >> 2;
    const int lc   = lane & 3;
    const int b    = blockIdx.z;
    const int h    = blockIdx.y;
    const int q0   = blockIdx.x * 128;

    // ---- load tiles ----
    {
        const __nv_bfloat16* Qgh = Qhi + ((size_t)(b * NMM + q0)) * DIM + h * HD;
        const __nv_bfloat16* Qgl = Qlo + ((size_t)(b * NMM + q0)) * DIM + h * HD;
#pragma unroll
        for (int it = 0; it < 4; it++) {
            int e = tid + it * 256;
            int r = e >> 3, s = e & 7;
            *(uint4*)&asm_[AT_QH + r * QSTR + s * 8] = *(const uint4*)(Qgh + (size_t)r * DIM + s * 8);
            *(uint4*)&asm_[AT_QL + r * QSTR + s * 8] = *(const uint4*)(Qgl + (size_t)r * DIM + s * 8);
        }
        const __nv_bfloat16* Kgh = KVhi + ((size_t)b * NSRC) * (2 * DIM) + h * HD;
        const __nv_bfloat16* Kgl = KVlo + ((size_t)b * NSRC) * (2 * DIM) + h * HD;
#pragma unroll
        for (int it = 0; it < 8; it++) {
            int e = tid + it * 256;
            int r = e >> 3, s = e & 7;
            size_t go = (size_t)r * (2 * DIM) + s * 8;
            *(uint4*)&asm_[AT_KH + r * QSTR + s * 8] = *(const uint4*)(Kgh + go);
            *(uint4*)&asm_[AT_KL + r * QSTR + s * 8] = *(const uint4*)(Kgl + go);
            *(uint4*)&asm_[AT_VH + r * QSTR + s * 8] = *(const uint4*)(Kgh + go + DIM);
            *(uint4*)&asm_[AT_VL + r * QSTR + s * 8] = *(const uint4*)(Kgl + go + DIM);
        }
    }
    __syncthreads();

    // ---- Q fragments (warp rows wid*16 .. +16) ----
    uint32_t qh[4][4], ql[4][4];
#pragma unroll
    for (int kt = 0; kt < 4; kt++) {
        const __nv_bfloat16* ph = asm_ + AT_QH + (wid * 16 + lr) * QSTR + kt * 16 + 2 * lc;
        const __nv_bfloat16* pl = asm_ + AT_QL + (wid * 16 + lr) * QSTR + kt * 16 + 2 * lc;
        qh[kt][0] = *(const uint32_t*)(ph);
        qh[kt][1] = *(const uint32_t*)(ph + 8 * QSTR);
        qh[kt][2] = *(const uint32_t*)(ph + 8);
        qh[kt][3] = *(const uint32_t*)(ph + 8 * QSTR + 8);
        ql[kt][0] = *(const uint32_t*)(pl);
        ql[kt][1] = *(const uint32_t*)(pl + 8 * QSTR);
        ql[kt][2] = *(const uint32_t*)(pl + 8);
        ql[kt][3] = *(const uint32_t*)(pl + 8 * QSTR + 8);
    }

    // ---- S = Q K^T (3-term split) ----
    float acc[32][4];
#pragma unroll
    for (int t = 0; t < 32; t++)
#pragma unroll
        for (int v = 0; v < 4; v++) acc[t][v] = 0.f;

#pragma unroll
    for (int nt = 0; nt < 32; nt++) {
        const __nv_bfloat16* kph = asm_ + AT_KH + (nt * 8 + lr) * QSTR + 2 * lc;
        const __nv_bfloat16* kpl = asm_ + AT_KL + (nt * 8 + lr) * QSTR + 2 * lc;
#pragma unroll
        for (int kt = 0; kt < 4; kt++) {
            uint32_t kh0 = *(const uint32_t*)(kph + kt * 16);
            uint32_t kh1 = *(const uint32_t*)(kph + kt * 16 + 8);
            uint32_t kl0 = *(const uint32_t*)(kpl + kt * 16);
            uint32_t kl1 = *(const uint32_t*)(kpl + kt * 16 + 8);
            mma16816(acc[nt], qh[kt][0], qh[kt][1], qh[kt][2], qh[kt][3], kh0, kh1);
            mma16816(acc[nt], qh[kt][0], qh[kt][1], qh[kt][2], qh[kt][3], kl0, kl1);
            mma16816(acc[nt], ql[kt][0], ql[kt][1], ql[kt][2], ql[kt][3], kh0, kh1);
        }
    }

    // ---- softmax (rows lr and lr+8 of this warp's 16) ----
    const float scale = 0.125f;
    float mx0 = -1e30f, mx1 = -1e30f;
#pragma unroll
    for (int t = 0; t < 32; t++) {
        mx0 = fmaxf(mx0, fmaxf(acc[t][0], acc[t][1]));
        mx1 = fmaxf(mx1, fmaxf(acc[t][2], acc[t][3]));
    }
    mx0 = fmaxf(mx0, __shfl_xor_sync(0xffffffffu, mx0, 1));
    mx0 = fmaxf(mx0, __shfl_xor_sync(0xffffffffu, mx0, 2));
    mx1 = fmaxf(mx1, __shfl_xor_sync(0xffffffffu, mx1, 1));
    mx1 = fmaxf(mx1, __shfl_xor_sync(0xffffffffu, mx1, 2));
    float s0 = 0.f, s1 = 0.f;
#pragma unroll
    for (int t = 0; t < 32; t++) {
        acc[t][0] = __expf((acc[t][0] - mx0) * scale); s0 += acc[t][0];
        acc[t][1] = __expf((acc[t][1] - mx0) * scale); s0 += acc[t][1];
        acc[t][2] = __expf((acc[t][2] - mx1) * scale); s1 += acc[t][2];
        acc[t][3] = __expf((acc[t][3] - mx1) * scale); s1 += acc[t][3];
    }
    s0 += __shfl_xor_sync(0xffffffffu, s0, 1);
    s0 += __shfl_xor_sync(0xffffffffu, s0, 2);
    s1 += __shfl_xor_sync(0xffffffffu, s1, 1);
    s1 += __shfl_xor_sync(0xffffffffu, s1, 2);
    float i0 = 1.f / s0, i1 = 1.f / s1;
#pragma unroll
    for (int t = 0; t < 32; t++) {
        acc[t][0] *= i0; acc[t][1] *= i0; acc[t][2] *= i1; acc[t][3] *= i1;
    }

    // ---- write attn probs (fp32, global, streaming) ----
    {
        float* ar0 = attn + ((size_t)((b * HEADS + h) * NMM) + q0 + wid * 16 + lr) * NSRC + 2 * lc;
        float* ar1 = ar0 + (size_t)8 * NSRC;
#pragma unroll
        for (int t = 0; t < 32; t++) {
            st_cs_f2(ar0 + t * 8, acc[t][0], acc[t][1]);
            st_cs_f2(ar1 + t * 8, acc[t][2], acc[t][3]);
        }
    }

    // ---- convert P to bf16 hi/lo A-fragments ----
    uint32_t ph[16][4], pl[16][4];
#pragma unroll
    for (int t = 0; t < 16; t++) {
        split2(acc[2 * t][0],     acc[2 * t][1],     ph[t][0], pl[t][0]);
        split2(acc[2 * t][2],     acc[2 * t][3],     ph[t][1], pl[t][1]);
        split2(acc[2 * t + 1][0], acc[2 * t + 1][1], ph[t][2], pl[t][2]);
        split2(acc[2 * t + 1][2], acc[2 * t + 1][3], ph[t][3], pl[t][3]);
    }

    // ---- O = P V (3-term split), V B-frags via ldmatrix.trans ----
    float oacc[8][4];
#pragma unroll
    for (int nd = 0; nd < 8; nd++)
#pragma unroll
        for (int v = 0; v < 4; v++) oacc[nd][v] = 0.f;

    uint32_t smb = smem_u32(asm_);
#pragma unroll
    for (int kt = 0; kt < 16; kt++) {
        uint32_t vrh = smb + (uint32_t)(AT_VH + (kt * 16 + (lane & 15)) * QSTR) * 2;
        uint32_t vrl = smb + (uint32_t)(AT_VL + (kt * 16 + (lane & 15)) * QSTR) * 2;
#pragma unroll
        for (int nd = 0; nd < 8; nd++) {
            uint32_t bh0, bh1, bl0, bl1;
            ldmx2t(bh0, bh1, vrh + nd * 16);
            ldmx2t(bl0, bl1, vrl + nd * 16);
            mma16816(oacc[nd], ph[kt][0], ph[kt][1], ph[kt][2], ph[kt][3], bh0, bh1);
            mma16816(oacc[nd], ph[kt][0], ph[kt][1], ph[kt][2], ph[kt][3], bl0, bl1);
            mma16816(oacc[nd], pl[kt][0], pl[kt][1], pl[kt][2], pl[kt][3], bh0, bh1);
        }
    }

    // ---- write O as bf16 hi/lo ----
    {
        size_t row0 = (size_t)(b * NMM + q0 + wid * 16 + lr);
        __nv_bfloat16* oh0 = Ohi + row0 * DIM + h * HD + 2 * lc;
        __nv_bfloat16* ol0 = Olo + row0 * DIM + h * HD + 2 * lc;
        __nv_bfloat16* oh1 = oh0 + (size_t)8 * DIM;
        __nv_bfloat16* ol1 = ol0 + (size_t)8 * DIM;
#pragma unroll
        for (int nd = 0; nd < 8; nd++) {
            uint32_t hh, ll;
            split2(oacc[nd][0], oacc[nd][1], hh, ll);
            *(uint32_t*)(oh0 + nd * 8) = hh;
            *(uint32_t*)(ol0 + nd * 8) = ll;
            split2(oacc[nd][2], oacc[nd][3], hh, ll);
            *(uint32_t*)(oh1 + nd * 8) = hh;
            *(uint32_t*)(ol1 + nd * 8) = ll;
        }
    }
}

// ---------------------------------------------------------------------------
extern "C" void kernel_launch(void* const* d_in, const int* in_sizes, int n_in,
                              void* d_out, int out_size)
{
    const float* xmm   = (const float*)d_in[0];
    const float* xv    = (const float*)d_in[1];
    const float* xa    = (const float*)d_in[2];
    const float* Wq    = (const float*)d_in[3];
    const float* Wkv   = (const float*)d_in[4];
    const float* Wproj = (const float*)d_in[5];
    const float* bproj = (const float*)d_in[6];

    float* out = (float*)d_out;

    float* attn_fb;
    cudaGetSymbolAddress((void**)&attn_fb, g_attn_fallback);

    __nv_bfloat16 *Axh, *Axl, *Ash, *Asl;
    __nv_bfloat16 *Qh, *Ql, *KVh, *KVl, *Oh, *Ol;
    __nv_bfloat16 *Wqh, *Wql, *Wkh, *Wkl, *Wph, *Wpl;
    cudaGetSymbolAddress((void**)&Axh, g_Axmm_hi);
    cudaGetSymbolAddress((void**)&Axl, g_Axmm_lo);
    cudaGetSymbolAddress((void**)&Ash, g_Asrc_hi);
    cudaGetSymbolAddress((void**)&Asl, g_Asrc_lo);
    cudaGetSymbolAddress((void**)&Qh,  g_Qh);
    cudaGetSymbolAddress((void**)&Ql,  g_Ql);
    cudaGetSymbolAddress((void**)&KVh, g_KVh);
    cudaGetSymbolAddress((void**)&KVl, g_KVl);
    cudaGetSymbolAddress((void**)&Oh,  g_Oh);
    cudaGetSymbolAddress((void**)&Ol,  g_Ol);
    cudaGetSymbolAddress((void**)&Wqh, g_Wqt_hi);
    cudaGetSymbolAddress((void**)&Wql, g_Wqt_lo);
    cudaGetSymbolAddress((void**)&Wkh, g_Wkvt_hi);
    cudaGetSymbolAddress((void**)&Wkl, g_Wkvt_lo);
    cudaGetSymbolAddress((void**)&Wph, g_Wpt_hi);
    cudaGetSymbolAddress((void**)&Wpl, g_Wpt_lo);

    const size_t out_elems  = (size_t)MQ * DIM;
    const size_t attn_elems = (size_t)BS * HEADS * NMM * NSRC;
    float* attn_out = ((size_t)out_size >= out_elems + attn_elems)
                        ? out + out_elems : attn_fb;

    cudaFuncSetAttribute(gemm_bf16s<true>, cudaFuncAttributeMaxDynamicSharedMemorySize, GEMM_SMEM);
    cudaFuncSetAttribute(gemm_bf16s<false>, cudaFuncAttributeMaxDynamicSharedMemorySize, GEMM_SMEM);
    cudaFuncSetAttribute(attn_mma, cudaFuncAttributeMaxDynamicSharedMemorySize, AT_SMEM_BYTES);

    // --- conversions ---
    split_plain<<<512, 256>>>(xmm, Axh, Axl, (size_t)MQ * DIM);
    split_concat<<<512, 256>>>(xv, xa, Ash, Asl);
    {
        dim3 b(32, 8);
        transpose_split<<<dim3(DIM / 32, DIM / 32), b>>>(Wq, Wqh, Wql, DIM, DIM);
        transpose_split<<<dim3(2 * DIM / 32, DIM / 32), b>>>(Wkv, Wkh, Wkl, DIM, 2 * DIM);
        transpose_split<<<dim3(DIM / 32, DIM / 32), b>>>(Wproj, Wph, Wpl, DIM, DIM);
    }

    // --- Q = xmm @ Wq  -> bf16 hi/lo ---
    gemm_bf16s<true><<<dim3(DIM / 128, MQ / 128), 256, GEMM_SMEM>>>(
        Axh, Axl, Wqh, Wql, nullptr, Qh, Ql, MQ, DIM, DIM, nullptr);
    // --- KV = concat(xv,xa) @ Wkv -> bf16 hi/lo ---
    gemm_bf16s<true><<<dim3(2 * DIM / 128, MQ / 128), 256, GEMM_SMEM>>>(
        Ash, Asl, Wkh, Wkl, nullptr, KVh, KVl, MQ, 2 * DIM, DIM, nullptr);
    // --- attention ---
    attn_mma<<<dim3(NMM / 128, HEADS, BS), 256, AT_SMEM_BYTES>>>(
        Qh, Ql, KVh, KVl, attn_out, Oh, Ol);
    // --- out = O @ Wproj + bproj (fp32) ---
    gemm_bf16s<false><<<dim3(DIM / 128, MQ / 128), 256, GEMM_SMEM>>>(
        Oh, Ol, Wph, Wpl, out, nullptr, nullptr, MQ, DIM, DIM, bproj);
}

// round 8
// speedup vs baseline: 3.0145x; 1.1255x over previous
#include <cuda_runtime.h>
#include <cuda_bf16.h>
#include <cstdint>
#include <math.h>

#define DIM   768
#define HEADS 12
#define HD    64
#define BS    32
#define NMM   256
#define NV    196
#define NA    60
#define NSRC  256            // NV + NA
#define MQ    (BS * NMM)     // 8192

// ---------------------------------------------------------------------------
// Scratch (static __device__ globals; allocation is forbidden)
// ---------------------------------------------------------------------------
__device__ float g_attn_fallback[(size_t)BS * HEADS * NMM * NSRC];

__device__ __nv_bfloat16 g_Axmm_hi[(size_t)MQ * DIM];
__device__ __nv_bfloat16 g_Axmm_lo[(size_t)MQ * DIM];
__device__ __nv_bfloat16 g_Asrc_hi[(size_t)MQ * DIM];
__device__ __nv_bfloat16 g_Asrc_lo[(size_t)MQ * DIM];
__device__ __nv_bfloat16 g_Qh [(size_t)MQ * DIM];
__device__ __nv_bfloat16 g_Ql [(size_t)MQ * DIM];
__device__ __nv_bfloat16 g_KVh[(size_t)MQ * 2 * DIM];
__device__ __nv_bfloat16 g_KVl[(size_t)MQ * 2 * DIM];
__device__ __nv_bfloat16 g_Oh [(size_t)MQ * DIM];
__device__ __nv_bfloat16 g_Ol [(size_t)MQ * DIM];
__device__ __nv_bfloat16 g_Wqt_hi [(size_t)DIM * DIM];
__device__ __nv_bfloat16 g_Wqt_lo [(size_t)DIM * DIM];
__device__ __nv_bfloat16 g_Wkvt_hi[(size_t)2 * DIM * DIM];
__device__ __nv_bfloat16 g_Wkvt_lo[(size_t)2 * DIM * DIM];
__device__ __nv_bfloat16 g_Wpt_hi [(size_t)DIM * DIM];
__device__ __nv_bfloat16 g_Wpt_lo [(size_t)DIM * DIM];

// ---------------------------------------------------------------------------
// helpers
// ---------------------------------------------------------------------------
__device__ __forceinline__ uint32_t smem_u32(const void* p) {
    uint32_t a;
    asm("{ .reg .u64 t; cvta.to.shared.u64 t, %1; cvt.u32.u64 %0, t; }" : "=r"(a) : "l"(p));
    return a;
}
__device__ __forceinline__ uint32_t pack_bf2(__nv_bfloat16 a, __nv_bfloat16 b) {
    __nv_bfloat162 t = __halves2bfloat162(a, b);
    return *reinterpret_cast<uint32_t*>(&t);
}
__device__ __forceinline__ void split2(float a, float b, uint32_t& hi, uint32_t& lo) {
    __nv_bfloat16 ha = __float2bfloat16(a), hb = __float2bfloat16(b);
    hi = pack_bf2(ha, hb);
    lo = pack_bf2(__float2bfloat16(a - __bfloat162float(ha)),
                  __float2bfloat16(b - __bfloat162float(hb)));
}
__device__ __forceinline__ void cp_async16(uint32_t saddr, const void* gptr) {
    asm volatile("cp.async.cg.shared.global [%0], [%1], 16;" :: "r"(saddr), "l"(gptr));
}
__device__ __forceinline__ void cp_commit() { asm volatile("cp.async.commit_group;"); }
template<int N_>
__device__ __forceinline__ void cp_wait() { asm volatile("cp.async.wait_group %0;" :: "n"(N_)); }

__device__ __forceinline__ void mma16816(float* c, uint32_t a0, uint32_t a1,
                                         uint32_t a2, uint32_t a3,
                                         uint32_t b0, uint32_t b1) {
    asm volatile(
        "mma.sync.aligned.m16n8k16.row.col.f32.bf16.bf16.f32 "
        "{%0,%1,%2,%3}, {%4,%5,%6,%7}, {%8,%9}, {%0,%1,%2,%3};"
        : "+f"(c[0]), "+f"(c[1]), "+f"(c[2]), "+f"(c[3])
        : "r"(a0), "r"(a1), "r"(a2), "r"(a3), "r"(b0), "r"(b1));
}
__device__ __forceinline__ void ldmx4(uint32_t* r, uint32_t saddr) {
    asm volatile("ldmatrix.sync.aligned.m8n8.x4.shared.b16 {%0,%1,%2,%3}, [%4];"
                 : "=r"(r[0]), "=r"(r[1]), "=r"(r[2]), "=r"(r[3]) : "r"(saddr));
}
__device__ __forceinline__ void ldmx4t(uint32_t* r, uint32_t saddr) {
    asm volatile("ldmatrix.sync.aligned.m8n8.x4.trans.shared.b16 {%0,%1,%2,%3}, [%4];"
                 : "=r"(r[0]), "=r"(r[1]), "=r"(r[2]), "=r"(r[3]) : "r"(saddr));
}
__device__ __forceinline__ void st_cs_f2(float* p, float x, float y) {
    asm volatile("st.global.cs.v2.f32 [%0], {%1, %2};" :: "l"(p), "f"(x), "f"(y) : "memory");
}

// ---------------------------------------------------------------------------
// Conversion kernels: fp32 -> (hi, lo) bf16 split
// ---------------------------------------------------------------------------
__global__ void split_plain(const float* __restrict__ X,
                            __nv_bfloat16* __restrict__ hi,
                            __nv_bfloat16* __restrict__ lo, size_t n) {
    for (size_t i = (size_t)blockIdx.x * blockDim.x + threadIdx.x; i < n;
         i += (size_t)gridDim.x * blockDim.x) {
        float x = X[i];
        __nv_bfloat16 h = __float2bfloat16(x);
        hi[i] = h;
        lo[i] = __float2bfloat16(x - __bfloat162float(h));
    }
}

__global__ void split_concat(const float* __restrict__ xv, const float* __restrict__ xa,
                             __nv_bfloat16* __restrict__ hi, __nv_bfloat16* __restrict__ lo) {
    size_t n = (size_t)MQ * DIM;
    for (size_t i = (size_t)blockIdx.x * blockDim.x + threadIdx.x; i < n;
         i += (size_t)gridDim.x * blockDim.x) {
        size_t row = i / DIM, col = i % DIM;
        int b = (int)(row >> 8), t = (int)(row & 255);
        float x = (t < NV) ? xv[((size_t)b * NV + t) * DIM + col]
                           : xa[((size_t)b * NA + (t - NV)) * DIM + col];
        __nv_bfloat16 h = __float2bfloat16(x);
        hi[i] = h;
        lo[i] = __float2bfloat16(x - __bfloat162float(h));
    }
}

// W [K][N] fp32 -> Wt [N][K] bf16 hi/lo
__global__ void transpose_split(const float* __restrict__ W,
                                __nv_bfloat16* __restrict__ Thi,
                                __nv_bfloat16* __restrict__ Tlo, int K, int N) {
    __shared__ float tile[32][33];
    int n0 = blockIdx.x * 32, k0 = blockIdx.y * 32;
    int tx = threadIdx.x, ty = threadIdx.y;     // (32, 8)
#pragma unroll
    for (int j = 0; j < 32; j += 8)
        tile[ty + j][tx] = W[(size_t)(k0 + ty + j) * N + (n0 + tx)];
    __syncthreads();
#pragma unroll
    for (int j = 0; j < 32; j += 8) {
        float v = tile[tx][ty + j];
        __nv_bfloat16 h = __float2bfloat16(v);
        size_t o = (size_t)(n0 + ty + j) * K + (k0 + tx);
        Thi[o] = h;
        Tlo[o] = __float2bfloat16(v - __bfloat162float(h));
    }
}

// ---------------------------------------------------------------------------
// HMMA split-bf16 GEMM: C[M,N] = A[M,K] @ Bt[N,K]^T
// CTA 128x128, 8 warps 64x32, K-chunk 32, double buffer, ldmatrix frags.
// ---------------------------------------------------------------------------
#define CK       32
#define SROW     40
#define TILE_BF  (128 * SROW)
#define ST_ELEMS (4 * TILE_BF)
#define GEMM_SMEM (2 * ST_ELEMS * 2)        // 81920 bytes

template<bool SPLIT>
__global__ void __launch_bounds__(256, 2) gemm_bf16s(
    const __nv_bfloat16* __restrict__ Ahi, const __nv_bfloat16* __restrict__ Alo,
    const __nv_bfloat16* __restrict__ Bhi, const __nv_bfloat16* __restrict__ Blo,
    float* __restrict__ C, __nv_bfloat16* __restrict__ Chi, __nv_bfloat16* __restrict__ Clo,
    int M, int N, int K, const float* __restrict__ bias)
{
    extern __shared__ __align__(16) __nv_bfloat16 sm[];
    const int tid  = threadIdx.x;
    const int wid  = tid >> 5;
    const int lane = tid & 31;
    const int wm   = (wid >> 2) * 64;
    const int wn   = (wid & 3) * 32;
    const int m0   = blockIdx.y * 128;
    const int n0   = blockIdx.x * 128;
    const int NC   = K / CK;                 // 24

    const int lr = lane >> 2;
    const int lc = (lane & 3) * 2;

    // ldmatrix per-lane row/col offsets
    const int arow = (lane & 7) + ((lane >> 3) & 1) * 8;   // A x4
    const int akof = (lane >> 4) * 8;
    const int brow = (lane & 7) + ((lane >> 4) << 3);      // B x4 (2 nt per call)
    const int bkof = ((lane >> 3) & 1) * 8;

    float acc[4][4][4];
#pragma unroll
    for (int i = 0; i < 4; i++)
#pragma unroll
        for (int j = 0; j < 4; j++)
#pragma unroll
            for (int v = 0; v < 4; v++) acc[i][j][v] = 0.f;

    uint32_t smb = smem_u32(sm);
    // per-thread static ldmatrix byte offsets (within a stage)
    const uint32_t offAh = (uint32_t)(0 * TILE_BF + (wm + arow) * SROW + akof) * 2;
    const uint32_t offAl = (uint32_t)(1 * TILE_BF + (wm + arow) * SROW + akof) * 2;
    const uint32_t offBh = (uint32_t)(2 * TILE_BF + (wn + brow) * SROW + bkof) * 2;
    const uint32_t offBl = (uint32_t)(3 * TILE_BF + (wn + brow) * SROW + bkof) * 2;

    auto load_chunk = [&](int c, int s) {
        uint32_t base = smb + (uint32_t)s * ST_ELEMS * 2;
        int k0 = c * CK;
#pragma unroll
        for (int it = 0; it < 2; it++) {
            int e   = tid + it * 256;
            int r   = e >> 2, seg = e & 3;
            uint32_t doff = (uint32_t)(r * SROW + seg * 8) * 2;
            size_t  goffA = (size_t)(m0 + r) * K + k0 + seg * 8;
            size_t  goffB = (size_t)(n0 + r) * K + k0 + seg * 8;
            cp_async16(base + 0 * TILE_BF * 2 + doff, Ahi + goffA);
            cp_async16(base + 1 * TILE_BF * 2 + doff, Alo + goffA);
            cp_async16(base + 2 * TILE_BF * 2 + doff, Bhi + goffB);
            cp_async16(base + 3 * TILE_BF * 2 + doff, Blo + goffB);
        }
        cp_commit();
    };

    load_chunk(0, 0);

    for (int c = 0; c < NC; c++) {
        int s = c & 1;
        if (c + 1 < NC) load_chunk(c + 1, (c + 1) & 1);
        if (c + 1 < NC) cp_wait<1>(); else cp_wait<0>();
        __syncthreads();

        uint32_t stg = smb + (uint32_t)s * ST_ELEMS * 2;

#pragma unroll
        for (int ks = 0; ks < 2; ks++) {
            uint32_t kbb = (uint32_t)(ks * 16) * 2;
            // B fragments: 2 x4 loads (hi), 2 x4 (lo) -> 4 nt blocks
            uint32_t bh[4][2], bl[4][2];
#pragma unroll
            for (int p = 0; p < 2; p++) {
                uint32_t t4[4];
                ldmx4(t4, stg + offBh + kbb + (uint32_t)(p * 16 * SROW) * 2);
                bh[2 * p][0] = t4[0]; bh[2 * p][1] = t4[1];
                bh[2 * p + 1][0] = t4[2]; bh[2 * p + 1][1] = t4[3];
                ldmx4(t4, stg + offBl + kbb + (uint32_t)(p * 16 * SROW) * 2);
                bl[2 * p][0] = t4[0]; bl[2 * p][1] = t4[1];
                bl[2 * p + 1][0] = t4[2]; bl[2 * p + 1][1] = t4[3];
            }
#pragma unroll
            for (int mt = 0; mt < 4; mt++) {
                uint32_t ah[4], al[4];
                ldmx4(ah, stg + offAh + kbb + (uint32_t)(mt * 16 * SROW) * 2);
                ldmx4(al, stg + offAl + kbb + (uint32_t)(mt * 16 * SROW) * 2);
#pragma unroll
                for (int nt = 0; nt < 4; nt++) {
                    mma16816(acc[mt][nt], ah[0], ah[1], ah[2], ah[3], bh[nt][0], bh[nt][1]);
                    mma16816(acc[mt][nt], ah[0], ah[1], ah[2], ah[3], bl[nt][0], bl[nt][1]);
                    mma16816(acc[mt][nt], al[0], al[1], al[2], al[3], bh[nt][0], bh[nt][1]);
                }
            }
        }
        __syncthreads();
    }

#pragma unroll
    for (int mt = 0; mt < 4; mt++) {
        int r0 = m0 + wm + mt * 16 + lr;
#pragma unroll
        for (int nt = 0; nt < 4; nt++) {
            int cc = n0 + wn + nt * 8 + lc;
            if (SPLIT) {
                uint32_t h0, l0, h1, l1;
                split2(acc[mt][nt][0], acc[mt][nt][1], h0, l0);
                split2(acc[mt][nt][2], acc[mt][nt][3], h1, l1);
                *(uint32_t*)(Chi + (size_t)r0 * N + cc)       = h0;
                *(uint32_t*)(Clo + (size_t)r0 * N + cc)       = l0;
                *(uint32_t*)(Chi + (size_t)(r0 + 8) * N + cc) = h1;
                *(uint32_t*)(Clo + (size_t)(r0 + 8) * N + cc) = l1;
            } else {
                float b0 = bias ? bias[cc]     : 0.f;
                float b1 = bias ? bias[cc + 1] : 0.f;
                float* p0 = C + (size_t)r0 * N + cc;
                float* p1 = C + (size_t)(r0 + 8) * N + cc;
                p0[0] = acc[mt][nt][0] + b0;
                p0[1] = acc[mt][nt][1] + b1;
                p1[0] = acc[mt][nt][2] + b0;
                p1[1] = acc[mt][nt][3] + b1;
            }
        }
    }
}

// ---------------------------------------------------------------------------
// HMMA flash-style attention. CTA = (q-tile 128, h, b), 256 thr (8 warps).
// Warp owns 16 q-rows x 256 keys. 3-term split everywhere. ldmatrix frags.
// ---------------------------------------------------------------------------
#define QSTR 72
#define AT_QH 0
#define AT_QL (128 * QSTR)
#define AT_KH (2 * 128 * QSTR)
#define AT_KL (AT_KH + 256 * QSTR)
#define AT_VH (AT_KH + 2 * 256 * QSTR)
#define AT_VL (AT_KH + 3 * 256 * QSTR)
#define AT_SMEM_ELE (AT_KH + 4 * 256 * QSTR)      // 92160 bf16
#define AT_SMEM_BYTES (AT_SMEM_ELE * 2)           // 184320

__global__ void __launch_bounds__(256) attn_mma(
    const __nv_bfloat16* __restrict__ Qhi, const __nv_bfloat16* __restrict__ Qlo,
    const __nv_bfloat16* __restrict__ KVhi, const __nv_bfloat16* __restrict__ KVlo,
    float* __restrict__ attn,
    __nv_bfloat16* __restrict__ Ohi, __nv_bfloat16* __restrict__ Olo)
{
    extern __shared__ __align__(16) __nv_bfloat16 asm_[];
    const int tid  = threadIdx.x;
    const int wid  = tid >> 5;
    const int lane = tid & 31;
    const int lr   = lane >> 2;
    const int lc   = lane & 3;
    const int b    = blockIdx.z;
    const int h    = blockIdx.y;
    const int q0   = blockIdx.x * 128;

    const int arow = (lane & 7) + ((lane >> 3) & 1) * 8;   // A-frag x4 offsets
    const int akof = (lane >> 4) * 8;
    const int brow = (lane & 7) + ((lane >> 4) << 3);      // B-frag x4 offsets
    const int bkof = ((lane >> 3) & 1) * 8;

    // ---- load tiles ----
    {
        const __nv_bfloat16* Qgh = Qhi + ((size_t)(b * NMM + q0)) * DIM + h * HD;
        const __nv_bfloat16* Qgl = Qlo + ((size_t)(b * NMM + q0)) * DIM + h * HD;
#pragma unroll
        for (int it = 0; it < 4; it++) {
            int e = tid + it * 256;
            int r = e >> 3, s = e & 7;
            *(uint4*)&asm_[AT_QH + r * QSTR + s * 8] = *(const uint4*)(Qgh + (size_t)r * DIM + s * 8);
            *(uint4*)&asm_[AT_QL + r * QSTR + s * 8] = *(const uint4*)(Qgl + (size_t)r * DIM + s * 8);
        }
        const __nv_bfloat16* Kgh = KVhi + ((size_t)b * NSRC) * (2 * DIM) + h * HD;
        const __nv_bfloat16* Kgl = KVlo + ((size_t)b * NSRC) * (2 * DIM) + h * HD;
#pragma unroll
        for (int it = 0; it < 8; it++) {
            int e = tid + it * 256;
            int r = e >> 3, s = e & 7;
            size_t go = (size_t)r * (2 * DIM) + s * 8;
            *(uint4*)&asm_[AT_KH + r * QSTR + s * 8] = *(const uint4*)(Kgh + go);
            *(uint4*)&asm_[AT_KL + r * QSTR + s * 8] = *(const uint4*)(Kgl + go);
            *(uint4*)&asm_[AT_VH + r * QSTR + s * 8] = *(const uint4*)(Kgh + go + DIM);
            *(uint4*)&asm_[AT_VL + r * QSTR + s * 8] = *(const uint4*)(Kgl + go + DIM);
        }
    }
    __syncthreads();

    uint32_t smb = smem_u32(asm_);

    // ---- Q fragments via ldmatrix.x4 ----
    uint32_t qh[4][4], ql[4][4];
    {
        uint32_t qoff = smb + (uint32_t)((wid * 16 + arow) * QSTR + akof) * 2;
#pragma unroll
        for (int kt = 0; kt < 4; kt++) {
            ldmx4(qh[kt], qoff + (uint32_t)(AT_QH * 2) + kt * 32);
            ldmx4(ql[kt], qoff + (uint32_t)(AT_QL * 2) + kt * 32);
        }
    }

    // ---- S = Q K^T (3-term split), K frags via ldmatrix.x4 ----
    float acc[32][4];
#pragma unroll
    for (int t = 0; t < 32; t++)
#pragma unroll
        for (int v = 0; v < 4; v++) acc[t][v] = 0.f;

    {
        uint32_t kbase = smb + (uint32_t)(brow * QSTR + bkof) * 2;
#pragma unroll
        for (int p = 0; p < 16; p++) {         // 16 key-pairs (16 keys each)
            uint32_t prow = kbase + (uint32_t)(p * 16 * QSTR) * 2;
#pragma unroll
            for (int kt = 0; kt < 4; kt++) {
                uint32_t kh4[4], kl4[4];
                ldmx4(kh4, prow + (uint32_t)(AT_KH * 2) + kt * 32);
                ldmx4(kl4, prow + (uint32_t)(AT_KL * 2) + kt * 32);
                mma16816(acc[2 * p],     qh[kt][0], qh[kt][1], qh[kt][2], qh[kt][3], kh4[0], kh4[1]);
                mma16816(acc[2 * p],     qh[kt][0], qh[kt][1], qh[kt][2], qh[kt][3], kl4[0], kl4[1]);
                mma16816(acc[2 * p],     ql[kt][0], ql[kt][1], ql[kt][2], ql[kt][3], kh4[0], kh4[1]);
                mma16816(acc[2 * p + 1], qh[kt][0], qh[kt][1], qh[kt][2], qh[kt][3], kh4[2], kh4[3]);
                mma16816(acc[2 * p + 1], qh[kt][0], qh[kt][1], qh[kt][2], qh[kt][3], kl4[2], kl4[3]);
                mma16816(acc[2 * p + 1], ql[kt][0], ql[kt][1], ql[kt][2], ql[kt][3], kh4[2], kh4[3]);
            }
        }
    }

    // ---- softmax (rows lr and lr+8 of this warp's 16) ----
    const float scale = 0.125f;
    float mx0 = -1e30f, mx1 = -1e30f;
#pragma unroll
    for (int t = 0; t < 32; t++) {
        mx0 = fmaxf(mx0, fmaxf(acc[t][0], acc[t][1]));
        mx1 = fmaxf(mx1, fmaxf(acc[t][2], acc[t][3]));
    }
    mx0 = fmaxf(mx0, __shfl_xor_sync(0xffffffffu, mx0, 1));
    mx0 = fmaxf(mx0, __shfl_xor_sync(0xffffffffu, mx0, 2));
    mx1 = fmaxf(mx1, __shfl_xor_sync(0xffffffffu, mx1, 1));
    mx1 = fmaxf(mx1, __shfl_xor_sync(0xffffffffu, mx1, 2));
    float s0 = 0.f, s1 = 0.f;
#pragma unroll
    for (int t = 0; t < 32; t++) {
        acc[t][0] = __expf((acc[t][0] - mx0) * scale); s0 += acc[t][0];
        acc[t][1] = __expf((acc[t][1] - mx0) * scale); s0 += acc[t][1];
        acc[t][2] = __expf((acc[t][2] - mx1) * scale); s1 += acc[t][2];
        acc[t][3] = __expf((acc[t][3] - mx1) * scale); s1 += acc[t][3];
    }
    s0 += __shfl_xor_sync(0xffffffffu, s0, 1);
    s0 += __shfl_xor_sync(0xffffffffu, s0, 2);
    s1 += __shfl_xor_sync(0xffffffffu, s1, 1);
    s1 += __shfl_xor_sync(0xffffffffu, s1, 2);
    float i0 = 1.f / s0, i1 = 1.f / s1;
#pragma unroll
    for (int t = 0; t < 32; t++) {
        acc[t][0] *= i0; acc[t][1] *= i0; acc[t][2] *= i1; acc[t][3] *= i1;
    }

    // ---- write attn probs (fp32, global, streaming) ----
    {
        float* ar0 = attn + ((size_t)((b * HEADS + h) * NMM) + q0 + wid * 16 + lr) * NSRC + 2 * lc;
        float* ar1 = ar0 + (size_t)8 * NSRC;
#pragma unroll
        for (int t = 0; t < 32; t++) {
            st_cs_f2(ar0 + t * 8, acc[t][0], acc[t][1]);
            st_cs_f2(ar1 + t * 8, acc[t][2], acc[t][3]);
        }
    }

    // ---- convert P to bf16 hi/lo A-fragments ----
    uint32_t ph[16][4], pl[16][4];
#pragma unroll
    for (int t = 0; t < 16; t++) {
        split2(acc[2 * t][0],     acc[2 * t][1],     ph[t][0], pl[t][0]);
        split2(acc[2 * t][2],     acc[2 * t][3],     ph[t][1], pl[t][1]);
        split2(acc[2 * t + 1][0], acc[2 * t + 1][1], ph[t][2], pl[t][2]);
        split2(acc[2 * t + 1][2], acc[2 * t + 1][3], ph[t][3], pl[t][3]);
    }

    // ---- O = P V (3-term split), V B-frags via ldmatrix.x4.trans ----
    float oacc[8][4];
#pragma unroll
    for (int nd = 0; nd < 8; nd++)
#pragma unroll
        for (int v = 0; v < 4; v++) oacc[nd][v] = 0.f;

    {
        // x4.trans: lanes 0-15 -> rows kt*16+0..15 at col ndp*16 ; lanes 16-31 same rows at col +8
        uint32_t vbase = smb + (uint32_t)((lane & 15) * QSTR + (lane >> 4) * 8) * 2;
#pragma unroll
        for (int kt = 0; kt < 16; kt++) {
            uint32_t vrow = vbase + (uint32_t)(kt * 16 * QSTR) * 2;
#pragma unroll
            for (int ndp = 0; ndp < 4; ndp++) {
                uint32_t vh4[4], vl4[4];
                ldmx4t(vh4, vrow + (uint32_t)(AT_VH * 2) + ndp * 32);
                ldmx4t(vl4, vrow + (uint32_t)(AT_VL * 2) + ndp * 32);
                mma16816(oacc[2 * ndp],     ph[kt][0], ph[kt][1], ph[kt][2], ph[kt][3], vh4[0], vh4[1]);
                mma16816(oacc[2 * ndp],     ph[kt][0], ph[kt][1], ph[kt][2], ph[kt][3], vl4[0], vl4[1]);
                mma16816(oacc[2 * ndp],     pl[kt][0], pl[kt][1], pl[kt][2], pl[kt][3], vh4[0], vh4[1]);
                mma16816(oacc[2 * ndp + 1], ph[kt][0], ph[kt][1], ph[kt][2], ph[kt][3], vh4[2], vh4[3]);
                mma16816(oacc[2 * ndp + 1], ph[kt][0], ph[kt][1], ph[kt][2], ph[kt][3], vl4[2], vl4[3]);
                mma16816(oacc[2 * ndp + 1], pl[kt][0], pl[kt][1], pl[kt][2], pl[kt][3], vh4[2], vh4[3]);
            }
        }
    }

    // ---- write O as bf16 hi/lo ----
    {
        size_t row0 = (size_t)(b * NMM + q0 + wid * 16 + lr);
        __nv_bfloat16* oh0 = Ohi + row0 * DIM + h * HD + 2 * lc;
        __nv_bfloat16* ol0 = Olo + row0 * DIM + h * HD + 2 * lc;
        __nv_bfloat16* oh1 = oh0 + (size_t)8 * DIM;
        __nv_bfloat16* ol1 = ol0 + (size_t)8 * DIM;
#pragma unroll
        for (int nd = 0; nd < 8; nd++) {
            uint32_t hh, ll;
            split2(oacc[nd][0], oacc[nd][1], hh, ll);
            *(uint32_t*)(oh0 + nd * 8) = hh;
            *(uint32_t*)(ol0 + nd * 8) = ll;
            split2(oacc[nd][2], oacc[nd][3], hh, ll);
            *(uint32_t*)(oh1 + nd * 8) = hh;
            *(uint32_t*)(ol1 + nd * 8) = ll;
        }
    }
}

// ---------------------------------------------------------------------------
extern "C" void kernel_launch(void* const* d_in, const int* in_sizes, int n_in,
                              void* d_out, int out_size)
{
    const float* xmm   = (const float*)d_in[0];
    const float* xv    = (const float*)d_in[1];
    const float* xa    = (const float*)d_in[2];
    const float* Wq    = (const float*)d_in[3];
    const float* Wkv   = (const float*)d_in[4];
    const float* Wproj = (const float*)d_in[5];
    const float* bproj = (const float*)d_in[6];

    float* out = (float*)d_out;

    float* attn_fb;
    cudaGetSymbolAddress((void**)&attn_fb, g_attn_fallback);

    __nv_bfloat16 *Axh, *Axl, *Ash, *Asl;
    __nv_bfloat16 *Qh, *Ql, *KVh, *KVl, *Oh, *Ol;
    __nv_bfloat16 *Wqh, *Wql, *Wkh, *Wkl, *Wph, *Wpl;
    cudaGetSymbolAddress((void**)&Axh, g_Axmm_hi);
    cudaGetSymbolAddress((void**)&Axl, g_Axmm_lo);
    cudaGetSymbolAddress((void**)&Ash, g_Asrc_hi);
    cudaGetSymbolAddress((void**)&Asl, g_Asrc_lo);
    cudaGetSymbolAddress((void**)&Qh,  g_Qh);
    cudaGetSymbolAddress((void**)&Ql,  g_Ql);
    cudaGetSymbolAddress((void**)&KVh, g_KVh);
    cudaGetSymbolAddress((void**)&KVl, g_KVl);
    cudaGetSymbolAddress((void**)&Oh,  g_Oh);
    cudaGetSymbolAddress((void**)&Ol,  g_Ol);
    cudaGetSymbolAddress((void**)&Wqh, g_Wqt_hi);
    cudaGetSymbolAddress((void**)&Wql, g_Wqt_lo);
    cudaGetSymbolAddress((void**)&Wkh, g_Wkvt_hi);
    cudaGetSymbolAddress((void**)&Wkl, g_Wkvt_lo);
    cudaGetSymbolAddress((void**)&Wph, g_Wpt_hi);
    cudaGetSymbolAddress((void**)&Wpl, g_Wpt_lo);

    const size_t out_elems  = (size_t)MQ * DIM;
    const size_t attn_elems = (size_t)BS * HEADS * NMM * NSRC;
    float* attn_out = ((size_t)out_size >= out_elems + attn_elems)
                        ? out + out_elems : attn_fb;

    cudaFuncSetAttribute(gemm_bf16s<true>, cudaFuncAttributeMaxDynamicSharedMemorySize, GEMM_SMEM);
    cudaFuncSetAttribute(gemm_bf16s<false>, cudaFuncAttributeMaxDynamicSharedMemorySize, GEMM_SMEM);
    cudaFuncSetAttribute(attn_mma, cudaFuncAttributeMaxDynamicSharedMemorySize, AT_SMEM_BYTES);

    // --- conversions (transposes first so ncu -s window lands on GEMM) ---
    {
        dim3 bb(32, 8);
        transpose_split<<<dim3(DIM / 32, DIM / 32), bb>>>(Wq, Wqh, Wql, DIM, DIM);
        transpose_split<<<dim3(2 * DIM / 32, DIM / 32), bb>>>(Wkv, Wkh, Wkl, DIM, 2 * DIM);
        transpose_split<<<dim3(DIM / 32, DIM / 32), bb>>>(Wproj, Wph, Wpl, DIM, DIM);
    }
    split_plain<<<512, 256>>>(xmm, Axh, Axl, (size_t)MQ * DIM);
    split_concat<<<512, 256>>>(xv, xa, Ash, Asl);

    // --- Q = xmm @ Wq  -> bf16 hi/lo ---
    gemm_bf16s<true><<<dim3(DIM / 128, MQ / 128), 256, GEMM_SMEM>>>(
        Axh, Axl, Wqh, Wql, nullptr, Qh, Ql, MQ, DIM, DIM, nullptr);
    // --- KV = concat(xv,xa) @ Wkv -> bf16 hi/lo ---
    gemm_bf16s<true><<<dim3(2 * DIM / 128, MQ / 128), 256, GEMM_SMEM>>>(
        Ash, Asl, Wkh, Wkl, nullptr, KVh, KVl, MQ, 2 * DIM, DIM, nullptr);
    // --- attention ---
    attn_mma<<<dim3(NMM / 128, HEADS, BS), 256, AT_SMEM_BYTES>>>(
        Qh, Ql, KVh, KVl, attn_out, Oh, Ol);
    // --- out = O @ Wproj + bproj (fp32) ---
    gemm_bf16s<false><<<dim3(DIM / 128, MQ / 128), 256, GEMM_SMEM>>>(
        Oh, Ol, Wph, Wpl, out, nullptr, nullptr, MQ, DIM, DIM, bproj);
}